// round 7
// baseline (speedup 1.0000x reference)
#include <cuda_runtime.h>
#include <cuda_bf16.h>
#include <cstdint>

#define NC 16
#define HWSZ (512*512)
#define NPIX (4*HWSZ)
#define NCHUNK (NPIX/16)          // 65536 chunks of 16 pixels
#define NCTA 148
#define NWARPS (NCTA*8)

// ---------------- mma helpers ----------------------------------------------
__device__ __forceinline__ uint32_t sptr(const void* p) {
    return (uint32_t)__cvta_generic_to_shared(p);
}
__device__ __forceinline__ void ldm4(uint32_t& r0, uint32_t& r1, uint32_t& r2, uint32_t& r3,
                                     uint32_t addr) {
    asm volatile("ldmatrix.sync.aligned.m8n8.x4.shared.b16 {%0,%1,%2,%3}, [%4];"
                 : "=r"(r0), "=r"(r1), "=r"(r2), "=r"(r3) : "r"(addr));
}
__device__ __forceinline__ void mma16816(float* c, const uint32_t* a, uint32_t b0, uint32_t b1) {
    asm volatile("mma.sync.aligned.m16n8k16.row.col.f32.bf16.bf16.f32 "
                 "{%0,%1,%2,%3}, {%4,%5,%6,%7}, {%8,%9}, {%0,%1,%2,%3};"
                 : "+f"(c[0]), "+f"(c[1]), "+f"(c[2]), "+f"(c[3])
                 : "r"(a[0]), "r"(a[1]), "r"(a[2]), "r"(a[3]), "r"(b0), "r"(b1));
}
__device__ __forceinline__ uint32_t pack2(float a, float b) {
    __nv_bfloat162 h = __floats2bfloat162_rn(a, b);
    return *reinterpret_cast<uint32_t*>(&h);
}
__device__ __forceinline__ uint32_t packrelu2(float a, float b) {
    return pack2(fmaxf(a, 0.0f), fmaxf(b, 0.0f));
}
__device__ __forceinline__ float wred(float s) {   // 32-lane sum reduce
    #pragma unroll
    for (int d = 16; d > 0; d >>= 1) s += __shfl_xor_sync(0xffffffffu, s, d);
    return s;
}

// ---------------- single fused kernel --------------------------------------
__global__ __launch_bounds__(256, 1)
void fused_kernel(const float* __restrict__ logits, float* __restrict__ out,
                  const float* __restrict__ E,
                  const float* __restrict__ aw1, const float* __restrict__ ab1,
                  const float* __restrict__ aw2, const float* __restrict__ ab2,
                  const float* __restrict__ w0,  const float* __restrict__ b0,
                  const float* __restrict__ w1,  const float* __restrict__ b1,
                  const float* __restrict__ fw,  const float* __restrict__ fb,
                  const float* __restrict__ ow,  const float* __restrict__ ob,
                  const float* __restrict__ gatep) {
    // ---- smem budget (static, <48KB):
    //   Es 8K + ows 8K + e12/Maggs union 8K + adjs 1K + c1/c2 + W1s 10240 + W2s 4864
    __shared__ __align__(16) float Es[16][128];
    __shared__ __align__(16) float ows[16][128];
    __shared__ __align__(16) float e12[2][16][64];   // later aliased as Maggs[128][16]
    __shared__ float adjs[16][16];
    __shared__ float rs[16];
    __shared__ float c1s[128], c2s[16];
    __shared__ __align__(16) __nv_bfloat16 W1s[128][40];
    __shared__ __align__(16) __nv_bfloat16 W2s[16][152];

    float (*Maggs)[16] = reinterpret_cast<float(*)[16]>(e12);   // union with e12

    const int tid = threadIdx.x;
    const int lane = tid & 31;
    const int w = tid >> 5;
    const int t = lane & 3;
    const int g = lane >> 2;

    // ======================= PROLOGUE: weight folds ========================
    for (int i = tid; i < 512; i += 256) {
        reinterpret_cast<float4*>(Es)[i]  = reinterpret_cast<const float4*>(E)[i];
        reinterpret_cast<float4*>(ows)[i] = reinterpret_cast<const float4*>(ow)[i];
    }
    const float gate = *gatep;
    __syncthreads();

    // e1/e2 = relu(E @ aw^T + ab): 2048 outputs, warp-reduce
    for (int r = 0; r < 256; r++) {
        const int o = w * 256 + r;
        const int which = o >> 10, i = (o >> 6) & 15, k = o & 63;
        const float* __restrict__ awp = which ? aw2 : aw1;
        const float4 ev = *reinterpret_cast<const float4*>(&Es[i][4 * lane]);
        const float4 wv = *reinterpret_cast<const float4*>(&awp[k * 128 + 4 * lane]);
        const float s = wred(ev.x * wv.x + ev.y * wv.y + ev.z * wv.z + ev.w * wv.w);
        if (lane == 0) {
            const float v = fmaxf(s + (which ? ab2 : ab1)[k], 0.0f);
            e12[which][i][k] = v;
        }
    }
    __syncthreads();

    // adj = sigmoid(e1 @ e2^T) + I
    {
        const int i = tid >> 4, j = tid & 15;
        float s0 = 0.f, s1 = 0.f, s2 = 0.f, s3 = 0.f;
        #pragma unroll
        for (int k = 0; k < 64; k += 4) {
            s0 += e12[0][i][k]     * e12[1][j][k];
            s1 += e12[0][i][k + 1] * e12[1][j][k + 1];
            s2 += e12[0][i][k + 2] * e12[1][j][k + 2];
            s3 += e12[0][i][k + 3] * e12[1][j][k + 3];
        }
        const float s = (s0 + s1) + (s2 + s3);
        adjs[i][j] = 1.0f / (1.0f + expf(-s)) + ((i == j) ? 1.0f : 0.0f);
    }
    __syncthreads();
    if (tid < 16) {
        float s = 0.0f;
        #pragma unroll
        for (int j = 0; j < 16; j++) s += adjs[tid][j];
        rs[tid] = 1.0f / s;
    }
    __syncthreads();          // e12 reads done -> safe to overwrite as Maggs

    // Magg = (adj_norm @ E)^T -> Maggs (union w/ e12) + W1s cols 16..31
    for (int idx = tid; idx < 2048; idx += 256) {
        const int c = idx >> 7, j = idx & 127;
        float s = 0.0f;
        #pragma unroll
        for (int i = 0; i < 16; i++) s += adjs[c][i] * Es[i][j];
        s *= rs[c];
        Maggs[j][c] = s;
        W1s[j][16 + c] = __float2bfloat16(s);
    }
    // A = W0 @ feat_w -> W1s cols 0..15 (warp-reduce; fw read via L1/L2)
    for (int r = 0; r < 256; r++) {
        const int o = w * 256 + r;
        const int j = o >> 4, c = o & 15;
        const float4 wv = *reinterpret_cast<const float4*>(&w0[j * 128 + 4 * lane]);
        const float f0 = fw[(4 * lane)     * 16 + c];
        const float f1 = fw[(4 * lane + 1) * 16 + c];
        const float f2 = fw[(4 * lane + 2) * 16 + c];
        const float f3 = fw[(4 * lane + 3) * 16 + c];
        const float s = wred(wv.x * f0 + wv.y * f1 + wv.z * f2 + wv.w * f3);
        if (lane == 0) W1s[j][c] = __float2bfloat16(s);
    }
    // Bw = out_w @ W1 -> W2s cols 0..127 (each warp: n=w and n=w+8)
    {
        float a0 = 0.f, a1 = 0.f, a2 = 0.f, a3 = 0.f;
        float d0 = 0.f, d1 = 0.f, d2 = 0.f, d3 = 0.f;
        const int n0 = w, n1 = w + 8;
        for (int j = 0; j < 128; j++) {
            const float4 wv = *reinterpret_cast<const float4*>(&w1[j * 128 + 4 * lane]);
            const float oa = ows[n0][j], obv = ows[n1][j];
            a0 += oa * wv.x; a1 += oa * wv.y; a2 += oa * wv.z; a3 += oa * wv.w;
            d0 += obv * wv.x; d1 += obv * wv.y; d2 += obv * wv.z; d3 += obv * wv.w;
        }
        W2s[n0][4 * lane]     = __float2bfloat16(a0);
        W2s[n0][4 * lane + 1] = __float2bfloat16(a1);
        W2s[n0][4 * lane + 2] = __float2bfloat16(a2);
        W2s[n0][4 * lane + 3] = __float2bfloat16(a3);
        W2s[n1][4 * lane]     = __float2bfloat16(d0);
        W2s[n1][4 * lane + 1] = __float2bfloat16(d1);
        W2s[n1][4 * lane + 2] = __float2bfloat16(d2);
        W2s[n1][4 * lane + 3] = __float2bfloat16(d3);
    }
    // c1 = W0 @ feat_b + b0 (warp-reduce, 16 per warp; fb from gmem)
    for (int r = 0; r < 16; r++) {
        const int j = w * 16 + r;
        const float4 wv = *reinterpret_cast<const float4*>(&w0[j * 128 + 4 * lane]);
        const float4 fv = *reinterpret_cast<const float4*>(&fb[4 * lane]);
        const float s = wred(wv.x * fv.x + wv.y * fv.y + wv.z * fv.z + wv.w * fv.w);
        if (lane == 0) c1s[j] = s + b0[j];
    }
    // c2 = out_w @ b1 + out_b (2 per warp; b1 from gmem)
    for (int r = 0; r < 2; r++) {
        const int n = w * 2 + r;
        const float4 ov = *reinterpret_cast<const float4*>(&ows[n][4 * lane]);
        const float4 bv = *reinterpret_cast<const float4*>(&b1[4 * lane]);
        const float s = wred(ov.x * bv.x + ov.y * bv.y + ov.z * bv.z + ov.w * bv.w);
        if (lane == 0) c2s[n] = s + ob[n];
    }
    __syncthreads();          // Maggs complete before S
    // S = out_w @ Magg -> W2s cols 128..143
    {
        const int n = tid >> 4, c = tid & 15;
        float s0 = 0.f, s1 = 0.f, s2 = 0.f, s3 = 0.f;
        #pragma unroll
        for (int j = 0; j < 128; j += 4) {
            s0 += ows[n][j]     * Maggs[j][c];
            s1 += ows[n][j + 1] * Maggs[j + 1][c];
            s2 += ows[n][j + 2] * Maggs[j + 2][c];
            s3 += ows[n][j + 3] * Maggs[j + 3][c];
        }
        W2s[n][128 + c] = __float2bfloat16((s0 + s1) + (s2 + s3));
    }
    __syncthreads();

    // ---- hoist weight fragments into registers (ldmatrix, once) ----
    const int brow16 = (lane & 7) + ((lane >= 16) ? 8 : 0);
    const int bcol8 = (lane & 8) ? 8 : 0;

    uint32_t fW1[8][8];
    #pragma unroll
    for (int ntp = 0; ntp < 8; ntp++) {
        ldm4(fW1[ntp][0], fW1[ntp][1], fW1[ntp][2], fW1[ntp][3],
             sptr(&W1s[16 * ntp + brow16][bcol8]));
        ldm4(fW1[ntp][4], fW1[ntp][5], fW1[ntp][6], fW1[ntp][7],
             sptr(&W1s[16 * ntp + brow16][16 + bcol8]));
    }
    uint32_t fW2[9][4];
    #pragma unroll
    for (int kb = 0; kb < 8; kb++)
        ldm4(fW2[kb][0], fW2[kb][1], fW2[kb][2], fW2[kb][3],
             sptr(&W2s[brow16][16 * kb + bcol8]));
    ldm4(fW2[8][0], fW2[8][1], fW2[8][2], fW2[8][3],
         sptr(&W2s[brow16][128 + bcol8]));

    // ======================= MAIN LOOP: warp-local =========================
    int offs[8];
    offs[0] = (2 * t)     * HWSZ + g;
    offs[1] = (2 * t + 1) * HWSZ + g;
    offs[2] = (2 * t)     * HWSZ + g + 8;
    offs[3] = (2 * t + 1) * HWSZ + g + 8;
    offs[4] = (2 * t + 8) * HWSZ + g;
    offs[5] = (2 * t + 9) * HWSZ + g;
    offs[6] = (2 * t + 8) * HWSZ + g + 8;
    offs[7] = (2 * t + 9) * HWSZ + g + 8;

    auto chunk_base = [](int ch) -> size_t {
        const int P = ch << 4;
        return (size_t)(P >> 18) * (NC * HWSZ) + (size_t)(P & (HWSZ - 1));
    };

    const int gw = (blockIdx.x << 3) | w;
    int ch = gw;
    size_t base = chunk_base(ch);
    float l[8];
    #pragma unroll
    for (int i = 0; i < 8; i++) l[i] = logits[base + offs[i]];

    while (ch < NCHUNK) {
        // ---- prefetch next chunk into registers ----
        const int nch = ch + NWARPS;
        size_t nbase = 0;
        float ln[8];
        if (nch < NCHUNK) {
            nbase = chunk_base(nch);
            #pragma unroll
            for (int i = 0; i < 8; i++) ln[i] = logits[nbase + offs[i]];
        }

        // ---- softmax over 16 classes (4-lane t-group shuffles) ----
        float mx = fmaxf(fmaxf(l[0], l[1]), fmaxf(l[4], l[5]));
        float my = fmaxf(fmaxf(l[2], l[3]), fmaxf(l[6], l[7]));
        mx = fmaxf(mx, __shfl_xor_sync(0xffffffffu, mx, 1));
        mx = fmaxf(mx, __shfl_xor_sync(0xffffffffu, mx, 2));
        my = fmaxf(my, __shfl_xor_sync(0xffffffffu, my, 1));
        my = fmaxf(my, __shfl_xor_sync(0xffffffffu, my, 2));
        const float p0 = __expf(l[0] - mx), p1 = __expf(l[1] - mx);
        const float p4 = __expf(l[4] - mx), p5 = __expf(l[5] - mx);
        const float q2 = __expf(l[2] - my), q3 = __expf(l[3] - my);
        const float q6 = __expf(l[6] - my), q7 = __expf(l[7] - my);
        float sx = (p0 + p1) + (p4 + p5);
        float sy = (q2 + q3) + (q6 + q7);
        sx += __shfl_xor_sync(0xffffffffu, sx, 1);
        sx += __shfl_xor_sync(0xffffffffu, sx, 2);
        sy += __shfl_xor_sync(0xffffffffu, sy, 1);
        sy += __shfl_xor_sync(0xffffffffu, sy, 2);
        const float ix = 1.0f / sx, iy = 1.0f / sy;

        // ---- build A fragments in registers ----
        uint32_t aL[4], aP[4];
        aL[0] = pack2(l[0], l[1]); aL[1] = pack2(l[2], l[3]);
        aL[2] = pack2(l[4], l[5]); aL[3] = pack2(l[6], l[7]);
        aP[0] = pack2(p0 * ix, p1 * ix); aP[1] = pack2(q2 * iy, q3 * iy);
        aP[2] = pack2(p4 * ix, p5 * ix); aP[3] = pack2(q6 * iy, q7 * iy);

        // ---- GEMM1: U[16,128] = [l|p] @ W1 + c1 ----
        float acc[16][4];
        #pragma unroll
        for (int nt = 0; nt < 16; nt++) {
            const float bv0 = c1s[8 * nt + 2 * t];
            const float bv1 = c1s[8 * nt + 2 * t + 1];
            acc[nt][0] = bv0; acc[nt][1] = bv1; acc[nt][2] = bv0; acc[nt][3] = bv1;
        }
        #pragma unroll
        for (int ntp = 0; ntp < 8; ntp++) {
            mma16816(acc[2 * ntp],     aL, fW1[ntp][0], fW1[ntp][1]);
            mma16816(acc[2 * ntp + 1], aL, fW1[ntp][2], fW1[ntp][3]);
            mma16816(acc[2 * ntp],     aP, fW1[ntp][4], fW1[ntp][5]);
            mma16816(acc[2 * ntp + 1], aP, fW1[ntp][6], fW1[ntp][7]);
        }

        // ---- GEMM2: R[16,16] = relu(U) @ Bw^T + p @ S^T + c2 ----
        float racc[2][4];
        #pragma unroll
        for (int nt = 0; nt < 2; nt++) {
            const float bv0 = c2s[8 * nt + 2 * t];
            const float bv1 = c2s[8 * nt + 2 * t + 1];
            racc[nt][0] = bv0; racc[nt][1] = bv1; racc[nt][2] = bv0; racc[nt][3] = bv1;
        }
        #pragma unroll
        for (int kb = 0; kb < 8; kb++) {
            uint32_t h[4];
            h[0] = packrelu2(acc[2 * kb][0],     acc[2 * kb][1]);
            h[1] = packrelu2(acc[2 * kb][2],     acc[2 * kb][3]);
            h[2] = packrelu2(acc[2 * kb + 1][0], acc[2 * kb + 1][1]);
            h[3] = packrelu2(acc[2 * kb + 1][2], acc[2 * kb + 1][3]);
            mma16816(racc[0], h, fW2[kb][0], fW2[kb][1]);
            mma16816(racc[1], h, fW2[kb][2], fW2[kb][3]);
        }
        mma16816(racc[0], aP, fW2[8][0], fW2[8][1]);
        mma16816(racc[1], aP, fW2[8][2], fW2[8][3]);

        // ---- epilogue: out = gate*r + logits (fp32 residual from regs) ----
        float* __restrict__ dst = out + base;
        dst[offs[0]] = fmaf(gate, racc[0][0], l[0]);
        dst[offs[1]] = fmaf(gate, racc[0][1], l[1]);
        dst[offs[2]] = fmaf(gate, racc[0][2], l[2]);
        dst[offs[3]] = fmaf(gate, racc[0][3], l[3]);
        dst[offs[4]] = fmaf(gate, racc[1][0], l[4]);
        dst[offs[5]] = fmaf(gate, racc[1][1], l[5]);
        dst[offs[6]] = fmaf(gate, racc[1][2], l[6]);
        dst[offs[7]] = fmaf(gate, racc[1][3], l[7]);

        // ---- rotate pipeline ----
        ch = nch;
        base = nbase;
        #pragma unroll
        for (int i = 0; i < 8; i++) l[i] = ln[i];
    }
}

// ---------------- launch -----------------------------------------------------
extern "C" void kernel_launch(void* const* d_in, const int* in_sizes, int n_in,
                              void* d_out, int out_size) {
    const float* logits = (const float*)d_in[0];
    const float* E      = (const float*)d_in[1];
    const float* aw1    = (const float*)d_in[2];
    const float* ab1    = (const float*)d_in[3];
    const float* aw2    = (const float*)d_in[4];
    const float* ab2    = (const float*)d_in[5];
    const float* w0     = (const float*)d_in[6];
    const float* b0     = (const float*)d_in[7];
    const float* w1     = (const float*)d_in[8];
    const float* b1     = (const float*)d_in[9];
    const float* fw     = (const float*)d_in[10];
    const float* fb     = (const float*)d_in[11];
    const float* ow     = (const float*)d_in[12];
    const float* ob     = (const float*)d_in[13];
    const float* gate   = (const float*)d_in[14];
    float* out = (float*)d_out;

    fused_kernel<<<NCTA, 256>>>(logits, out, E, aw1, ab1, aw2, ab2,
                                w0, b0, w1, b1, fw, fb, ow, ob, gate);
}